// round 4
// baseline (speedup 1.0000x reference)
#include <cuda_runtime.h>

// out4[((b*H+y)*W+x)*768 + ch*4 + i] = float4{ in[b,ch,y+i-3,x-2 .. x+1] },
// zero-padded, with lanes z,w zeroed when i==3. B=8, C=192, H=W=48.
// Block = (b, y, 4-wide x-tile). Smem: [768 chi-rows][pitch 7] = 21504 B.

#define B_   8
#define C_   192
#define H_   48
#define W_   48
#define TX   4
#define XT   (W_ / TX)             // 12
#define PITCH 7                    // cols x0-2 .. x0+4
#define SELEMS (C_ * 4 * PITCH)    // 5376 floats = 21504 B
#define LOAD_ITERS (SELEMS / 256)  // 21

__global__ void __launch_bounds__(256, 8)
block_sample_smem(const float* __restrict__ in, float4* __restrict__ out)
{
    __shared__ float s[SELEMS];

    const int tid = threadIdx.x;
    int bid = blockIdx.x;
    const int xt = bid % XT;  bid /= XT;
    const int y  = bid % H_;
    const int b  = bid / H_;
    const int x0 = xt * TX;

    // ---- load: rows y-3..y, cols x0-2..x0+4, all 192 channels ----
    #pragma unroll
    for (int k = 0; k < LOAD_ITERS; k++) {
        const int idx = k * 256 + tid;
        const int sc  = idx % PITCH;       // 0..6
        const int rf  = idx / PITCH;       // ch*4 + r
        const int gy  = y + (rf & 3) - 3;  // <= 47 always
        const int gx  = x0 - 2 + sc;       // -2..48
        float v = 0.f;
        if (gy >= 0 && gx >= 0 && gx < W_)
            v = __ldg(in + ((b * C_ + (rf >> 2)) * H_ + gy) * W_ + gx);
        s[idx] = v;
    }
    __syncthreads();

    // ---- store: per chi, read 7-word window once, emit 4 sliding float4s ----
    float4* const obase = out + (long)((b * H_ + y) * W_ + x0) * (C_ * 4);
    #pragma unroll
    for (int sub = 0; sub < 3; sub++) {                 // 768 = 3*256
        const int chi = sub * 256 + tid;                // ch*4 + i
        const bool m  = (chi & 3) == 3;                 // i == 3 -> mask z,w
        const float* row = &s[chi * PITCH];
        const float r0 = row[0], r1 = row[1], r2 = row[2], r3 = row[3];
        const float r4 = row[4], r5 = row[5], r6 = row[6];
        const float m2 = m ? 0.f : r2;
        const float m3 = m ? 0.f : r3;
        const float m4 = m ? 0.f : r4;
        const float m5 = m ? 0.f : r5;
        const float m6 = m ? 0.f : r6;
        float4* o = obase + chi;
        o[0]           = make_float4(r0, r1, m2, m3);
        o[C_ * 4]      = make_float4(r1, r2, m3, m4);
        o[2 * C_ * 4]  = make_float4(r2, r3, m4, m5);
        o[3 * C_ * 4]  = make_float4(r3, r4, m5, m6);
    }
}

extern "C" void kernel_launch(void* const* d_in, const int* in_sizes, int n_in,
                              void* d_out, int out_size)
{
    const float* in  = (const float*)d_in[0];
    float4*      out = (float4*)d_out;

    const int blocks = B_ * H_ * XT;   // 4608
    block_sample_smem<<<blocks, 256>>>(in, out);
}

// round 5
// speedup vs baseline: 1.1328x; 1.1328x over previous
#include <cuda_runtime.h>

// out4[((b*H+y)*W+x)*768 + ch*4 + i] = float4{ in[b,ch,y+i-3, x-2..x+1] },
// zero-padded; lanes z,w zeroed when i==3. B=8, C=192, H=W=48.
// Block = (b, y, 4-wide x-tile). Smem: [768 chi][pitch 8] = 24576 B.

#define B_   8
#define C_   192
#define H_   48
#define W_   48
#define TX   4
#define XT   (W_ / TX)             // 12
#define PITCH 8                    // cols x0-2 .. x0+5 (word 7 unused by stores)
#define SELEMS (C_ * 4 * PITCH)    // 6144 floats = 24576 B
#define LOAD_ITERS (SELEMS / 256)  // 24

__global__ void __launch_bounds__(256)
block_sample_smem(const float* __restrict__ in, float4* __restrict__ out)
{
    __shared__ float s[SELEMS];

    const int tid = threadIdx.x;
    int bid = blockIdx.x;
    const int xt = bid % XT;  bid /= XT;
    const int y  = bid % H_;
    const int b  = bid / H_;
    const int x0 = xt * TX;

    // ---- load: rows y-3..y, cols x0-2..x0+5, all 192 channels (bit-ops only) ----
    #pragma unroll
    for (int k = 0; k < LOAD_ITERS; k++) {
        const int idx = k * 256 + tid;
        const int sc  = idx & 7;           // 0..7
        const int rf  = idx >> 3;          // ch*4 + r
        const int gy  = y + (rf & 3) - 3;  // <= 47 always
        const int gx  = x0 - 2 + sc;       // -2 .. 49
        float v = 0.f;
        if (gy >= 0 && gx >= 0 && gx < W_)
            v = __ldg(in + ((b * C_ + (rf >> 2)) * H_ + gy) * W_ + gx);
        s[idx] = v;
    }
    __syncthreads();

    // ---- store: per chi read window as two float4 LDS, emit 4 sliding STG.128 ----
    float4* const obase = out + (long)((b * H_ + y) * W_ + x0) * (C_ * 4);
    #pragma unroll
    for (int sub = 0; sub < 3; sub++) {                 // 768 = 3*256
        const int chi = sub * 256 + tid;                // ch*4 + i
        const bool m  = (chi & 3) == 3;                 // i == 3 -> mask z,w
        const float4 lo = *reinterpret_cast<const float4*>(&s[chi * PITCH]);
        const float4 hi = *reinterpret_cast<const float4*>(&s[chi * PITCH + 4]);
        const float r0 = lo.x, r1 = lo.y;
        const float m2 = m ? 0.f : lo.z;
        const float m3 = m ? 0.f : lo.w;
        const float m4 = m ? 0.f : hi.x;
        const float m5 = m ? 0.f : hi.y;
        const float m6 = m ? 0.f : hi.z;
        const float r2 = lo.z, r3 = lo.w, r4 = hi.x;
        float4* o = obase + chi;
        __stcs(o,              make_float4(r0, r1, m2, m3));
        __stcs(o + C_ * 4,     make_float4(r1, r2, m3, m4));
        __stcs(o + 2 * C_ * 4, make_float4(r2, r3, m4, m5));
        __stcs(o + 3 * C_ * 4, make_float4(r3, r4, m5, m6));
    }
}

extern "C" void kernel_launch(void* const* d_in, const int* in_sizes, int n_in,
                              void* d_out, int out_size)
{
    const float* in  = (const float*)d_in[0];
    float4*      out = (float4*)d_out;

    const int blocks = B_ * H_ * XT;   // 4608
    block_sample_smem<<<blocks, 256>>>(in, out);
}